// round 3
// baseline (speedup 1.0000x reference)
#include <cuda_runtime.h>
#include <math.h>

// Problem constants (fixed shapes per reference)
#define BDIM    512          // number of events (scan length)
#define DEG     16           // neighbors per event
#define NSLOT   17           // write slots per step: w=0 event, w=1..16 neighbors
#define NREAD   22           // read slots per step: 17 (u) + 5 (u_neg)
#define NEGK    5
#define H       256
#define NNODES  200000
#define HBITS   15
#define HSIZE   (1 << HBITS)
#define HMASK   (HSIZE - 1)
#define HK      16           // max writers tracked per row (expected max ~3)
#define CPR     128          // z0-copy rows per work chunk
#define NCHUNK  ((NNODES + CPR - 1) / CPR)
#define TOTAL_WORK (BDIM + NCHUNK)

// ------------------------- persistent device state -------------------------
__device__ __align__(16) float g_staging[BDIM][NSLOT][H];   // 8.9 MB, per-step row versions
__device__ int g_done[BDIM];
__device__ int g_src[BDIM][NREAD];     // -1 => z0[row], else (t'<<5)|w'
__device__ int g_ctr;
__device__ int g_hrow[HSIZE];
__device__ int g_hcnt[HSIZE];
__device__ int g_hent[HSIZE][HK];      // e = (t<<10)|(prio<<5)|w ; prio: neigh j -> j, event -> 16

// ------------------------------- helpers -----------------------------------
__device__ __forceinline__ unsigned hashrow(int row) {
    return ((unsigned)row * 2654435761u) >> (32 - HBITS);
}
__device__ __forceinline__ int ld_acq(const int* p) {
    int v; asm volatile("ld.acquire.gpu.b32 %0, [%1];" : "=r"(v) : "l"(p) : "memory"); return v;
}
__device__ __forceinline__ void st_rel(int* p, int v) {
    asm volatile("st.release.gpu.b32 [%0], %1;" :: "l"(p), "r"(v) : "memory");
}
__device__ __forceinline__ unsigned long long pk2(float lo, float hi) {
    unsigned long long r;
    asm("mov.b64 %0, {%1, %2};" : "=l"(r) : "f"(lo), "f"(hi));
    return r;
}
__device__ __forceinline__ void upk2(unsigned long long v, float& lo, float& hi) {
    asm("mov.b64 {%0, %1}, %2;" : "=f"(lo), "=f"(hi) : "l"(v));
}
// packed fp32x2 FMA: d = a*b + d  (2x FFMA throughput on sm_103a)
__device__ __forceinline__ void fma2(unsigned long long& d, unsigned long long a, unsigned long long b) {
    asm("fma.rn.f32x2 %0, %1, %2, %0;" : "+l"(d) : "l"(a), "l"(b));
}
__device__ __forceinline__ float sigmoidf_(float x) { return 1.0f / (1.0f + expf(-x)); }

// ------------------------------- kernels -----------------------------------
__global__ void k_clear() {
    int i = blockIdx.x * blockDim.x + threadIdx.x;
    if (i < HSIZE) { g_hrow[i] = -1; g_hcnt[i] = 0; }
    if (i < BDIM) g_done[i] = 0;
    if (i == 0) g_ctr = 0;
}

// Insert the 512*17 writes into an open-addressing hash keyed by row id.
__global__ void k_insert(const int* __restrict__ u) {
    int idx = blockIdx.x * blockDim.x + threadIdx.x;
    if (idx >= BDIM * NSLOT) return;
    int t = idx / NSLOT, w = idx % NSLOT;
    int row = u[t * NSLOT + w];
    int prio = (w == 0) ? 16 : (w - 1);            // event applied last; later neighbor wins
    int e = (t << 10) | (prio << 5) | w;
    unsigned hsh = hashrow(row);
    for (;;) {
        int cur = atomicCAS(&g_hrow[hsh], -1, row);
        if (cur == -1 || cur == row) {
            int c = atomicAdd(&g_hcnt[hsh], 1);
            if (c < HK) g_hent[hsh][c] = e;
            break;
        }
        hsh = (hsh + 1) & HMASK;
    }
}

// For each of 512*22 reads, find the latest writer (t',prio) with t' < t.
__global__ void k_resolve(const int* __restrict__ u, const int* __restrict__ u_neg) {
    int idx = blockIdx.x * blockDim.x + threadIdx.x;
    if (idx >= BDIM * NREAD) return;
    int t = idx / NREAD, r = idx % NREAD;
    int row = (r < NSLOT) ? u[t * NSLOT + r] : u_neg[t * NEGK + (r - NSLOT)];
    unsigned hsh = hashrow(row);
    int src = -1, bestkey = -1;
    for (;;) {
        int cur = g_hrow[hsh];
        if (cur == -1) break;
        if (cur == row) {
            int c = g_hcnt[hsh]; if (c > HK) c = HK;
            for (int i = 0; i < c; ++i) {
                int e = g_hent[hsh][i];
                if ((e >> 10) < t) {
                    int key = e >> 5;                // t*32 + prio
                    if (key > bestkey) { bestkey = key; src = ((e >> 10) << 5) | (e & 31); }
                }
            }
            break;
        }
        hsh = (hsh + 1) & HMASK;
    }
    g_src[t][r] = src;
}

// Persistent main kernel: dynamic work ids [0,512) = event steps,
// [512, 512+NCHUNK) = z0 -> out copy chunks (overlaps dependency stalls).
__global__ void __launch_bounds__(256, 1) k_main(
    const int* __restrict__ u, const float* __restrict__ td,
    const float* __restrict__ time_bar, const float* __restrict__ time_cur,
    const int* __restrict__ u_neg, const float* __restrict__ z0,
    const float* __restrict__ Wh,   const float* __restrict__ bh,
    const float* __restrict__ We2n, const float* __restrict__ be2n,
    const float* __restrict__ Wre,  const float* __restrict__ bre,
    const float* __restrict__ Wrn,  const float* __restrict__ brn,
    const float* __restrict__ Wt,   const float* __restrict__ bt,
    const float* __restrict__ Wom,  const float* __restrict__ bom_p,
    const float* __restrict__ wt_p, const float* __restrict__ alpha_p,
    const float* __restrict__ psi_p, float* __restrict__ out)
{
    __shared__ __align__(16) float s_znb[DEG][H];
    __shared__ __align__(16) float s_emb[H];
    __shared__ __align__(16) float s_mean[H];
    __shared__ float s_td[NSLOT][4];
    __shared__ int s_step;

    const int tid = threadIdx.x;
    const int lane = tid & 31, wid = tid >> 5;
    const float w_t = *wt_p, alpha = *alpha_p, psi = *psi_p;
    const float bom = *bom_p;
    const float inv_psi = 1.0f / (psi + 1e-7f);
    float* outz = out + (BDIM + BDIM * NEGK);

    for (;;) {
        __syncthreads();                      // protect s_step / smem reuse across iterations
        if (tid == 0) s_step = atomicAdd(&g_ctr, 1);
        __syncthreads();
        const int s = s_step;
        if (s >= TOTAL_WORK) break;

        if (s >= BDIM) {
            // ---- copy chunk: z0 rows -> output z_final region ----
            int c = s - BDIM;
            int r0 = c * CPR;
            int nrow = NNODES - r0; if (nrow > CPR) nrow = CPR;
            const float4* src = (const float4*)z0 + (size_t)r0 * (H / 4);
            float4* dst = (float4*)outz + (size_t)r0 * (H / 4);
            int n4 = nrow * (H / 4);
            for (int i = tid; i < n4; i += 256) dst[i] = src[i];
            continue;
        }

        // ---------------- event step s ----------------
        // wait for producer steps of our 22 read rows (rarely needed)
        if (tid < NREAD) {
            int sv = g_src[s][tid];
            if (sv >= 0) {
                int* flag = &g_done[sv >> 5];
                while (ld_acq(flag) == 0) __nanosleep(64);
            }
        }
        // normalized time deltas (threads 32..99, disjoint from waiters)
        if (tid >= 32 && tid < 32 + NSLOT * 4) {
            int q = tid - 32;
            const float inv_sd[4] = {1.f/50.f, 1.f/7.f, 1.f/15.f, 1.f/15.f};
            s_td[q >> 2][q & 3] = td[(s * NSLOT + (q >> 2)) * 4 + (q & 3)] * inv_sd[q & 3];
        }
        __syncthreads();

        // load the 17 u-rows (emb_u + 16 neighbors) from the resolved version
        for (int r = wid; r < NSLOT; r += 8) {
            int sv = g_src[s][r];
            const float4* src4 = (sv >= 0)
                ? (const float4*)g_staging[sv >> 5][sv & 31]
                : (const float4*)(z0 + (size_t)u[s * NSLOT + r] * H);
            float4* dst4 = (r == 0) ? (float4*)s_emb : (float4*)s_znb[r - 1];
            dst4[lane]      = src4[lane];
            dst4[lane + 32] = src4[lane + 32];
        }
        __syncthreads();

        // mean over 16 neighbor rows (fold: mean(z_nb) @ Wh^T == mean(z_nb @ Wh^T))
        {
            float acc = 0.f;
            #pragma unroll
            for (int j = 0; j < DEG; ++j) acc += s_znb[j][tid];
            s_mean[tid] = acc * (1.0f / DEG);
        }

        // Hawkes lambdas (warps 0..4: negatives; warp 5: positive)
        if (wid < NEGK) {
            int node = u_neg[s * NEGK + wid];
            int sv = g_src[s][NSLOT + wid];
            const float* srcp = (sv >= 0) ? g_staging[sv >> 5][sv & 31]
                                          : (z0 + (size_t)node * H);
            float acc = 0.f;
            for (int i = lane; i < H; i += 32) acc += srcp[i] * Wom[i];
            #pragma unroll
            for (int o = 16; o; o >>= 1) acc += __shfl_down_sync(0xffffffffu, acc, o);
            if (lane == 0) {
                float ts = time_cur[s] - time_bar[(size_t)s * NNODES + node];
                float g = acc + bom + alpha * expf(-w_t * (ts * (1.0f / 86400.0f)));
                float gp = fminf(fmaxf(g * inv_psi, -75.f), 75.f);
                out[BDIM + s * NEGK + wid] = psi * log1pf(expf(gp)) * (1.0f / NEGK);
            }
        } else if (wid == 5) {
            float acc = 0.f;
            for (int i = lane; i < H; i += 32) acc += s_emb[i] * Wom[i];
            #pragma unroll
            for (int o = 16; o; o >>= 1) acc += __shfl_down_sync(0xffffffffu, acc, o);
            if (lane == 0) {
                float ts = time_cur[s] - s_td[0][0];
                float g = acc + bom + alpha * expf(-w_t * (ts * (1.0f / 86400.0f)));
                float gp = fminf(fmaxf(g * inv_psi, -75.f), 75.f);
                out[s] = psi * log1pf(expf(gp));
            }
        }
        __syncthreads();   // s_mean ready for all

        // ---- three matvecs (thread tid owns output column h = tid) ----
        const int h = tid;
        float ah = 0.f, ae = 0.f, an = 0.f;
        {
            const float4* wh4 = (const float4*)(Wh   + (size_t)h * H);
            const float4* we4 = (const float4*)(Wre  + (size_t)h * H);
            const float4* wn4 = (const float4*)(We2n + (size_t)h * H);
            #pragma unroll 8
            for (int i4 = 0; i4 < H / 4; ++i4) {
                float4 a = wh4[i4], b = we4[i4], c = wn4[i4];
                int i = i4 * 4;
                float m0 = s_mean[i], m1 = s_mean[i+1], m2 = s_mean[i+2], m3 = s_mean[i+3];
                float e0 = s_emb[i],  e1 = s_emb[i+1],  e2 = s_emb[i+2],  e3 = s_emb[i+3];
                ah += a.x*m0 + a.y*m1 + a.z*m2 + a.w*m3;
                ae += b.x*e0 + b.y*e1 + b.z*e2 + b.w*e3;
                an += c.x*e0 + c.y*e1 + c.z*e2 + c.w*e3;
            }
        }
        float4 wtr = *(const float4*)(Wt + (size_t)h * 4);
        float btv = bt[h];
        {
            float tf0 = btv + wtr.x*s_td[0][0] + wtr.y*s_td[0][1] + wtr.z*s_td[0][2] + wtr.w*s_td[0][3];
            g_staging[s][0][h] = sigmoidf_(ah + bh[h] + ae + bre[h] + tf0);   // z_ev
        }

        // ---- main GEMM: 16 x 256 @ 256 x 256, packed f32x2 FMAs ----
        unsigned long long acc2[DEG];
        #pragma unroll
        for (int j = 0; j < DEG; ++j) acc2[j] = 0ull;
        const float4* wr4 = (const float4*)(Wrn + (size_t)h * H);
        #pragma unroll 2
        for (int i4 = 0; i4 < H / 4; ++i4) {
            float4 w = wr4[i4];
            unsigned long long w01 = pk2(w.x, w.y);
            unsigned long long w23 = pk2(w.z, w.w);
            int i = i4 * 4;
            #pragma unroll
            for (int j = 0; j < DEG; ++j) {
                unsigned long long z01 = *(const unsigned long long*)&s_znb[j][i];     // LDS.64 broadcast
                unsigned long long z23 = *(const unsigned long long*)&s_znb[j][i + 2];
                fma2(acc2[j], w01, z01);
                fma2(acc2[j], w23, z23);
            }
        }
        float cmn = brn[h] + an + be2n[h];
        #pragma unroll
        for (int j = 0; j < DEG; ++j) {
            float lo, hi; upk2(acc2[j], lo, hi);
            float tf = btv + wtr.x*s_td[1+j][0] + wtr.y*s_td[1+j][1]
                           + wtr.z*s_td[1+j][2] + wtr.w*s_td[1+j][3];
            g_staging[s][1 + j][h] = sigmoidf_(lo + hi + cmn + tf);          // z_nb_new[j]
        }

        __threadfence();                 // make this thread's staging writes device-visible
        __syncthreads();                 // all threads' writes fenced
        if (tid == 0) st_rel(&g_done[s], 1);
    }
}

// Scatter final row versions (last writer per touched row) over the copied z0.
__global__ void k_scatter(float* __restrict__ outz) {
    int b = blockIdx.x;
    int c = g_hcnt[b];
    if (c <= 0) return;
    if (c > HK) c = HK;
    int bestkey = -1, beste = 0;
    for (int i = 0; i < c; ++i) {
        int e = g_hent[b][i];
        int key = e >> 5;
        if (key > bestkey) { bestkey = key; beste = e; }
    }
    int t = beste >> 10, w = beste & 31;
    int row = g_hrow[b];
    const float4* src = (const float4*)g_staging[t][w];
    float4* dst = (float4*)outz + (size_t)row * (H / 4);
    dst[threadIdx.x] = src[threadIdx.x];
}

// ------------------------------- launch ------------------------------------
extern "C" void kernel_launch(void* const* d_in, const int* in_sizes, int n_in,
                              void* d_out, int out_size) {
    const int*   u     = (const int*)  d_in[0];
    const float* td    = (const float*)d_in[1];
    const float* tbar  = (const float*)d_in[2];
    const float* tcur  = (const float*)d_in[3];
    // d_in[4] significance, d_in[5] magnitudo: unused by reference
    const int*   uneg  = (const int*)  d_in[6];
    const float* z0    = (const float*)d_in[7];
    const float* Wh    = (const float*)d_in[8];
    const float* bh    = (const float*)d_in[9];
    const float* We2n  = (const float*)d_in[10];
    const float* be2n  = (const float*)d_in[11];
    const float* Wre   = (const float*)d_in[12];
    const float* bre   = (const float*)d_in[13];
    const float* Wrn   = (const float*)d_in[14];
    const float* brn   = (const float*)d_in[15];
    const float* Wt    = (const float*)d_in[16];
    const float* bt    = (const float*)d_in[17];
    const float* Wom   = (const float*)d_in[18];
    const float* bom   = (const float*)d_in[19];
    const float* wt    = (const float*)d_in[20];
    const float* alpha = (const float*)d_in[21];
    const float* psi   = (const float*)d_in[22];
    float* out = (float*)d_out;

    k_clear  <<<(HSIZE + 255) / 256, 256>>>();
    k_insert <<<(BDIM * NSLOT + 255) / 256, 256>>>(u);
    k_resolve<<<(BDIM * NREAD + 255) / 256, 256>>>(u, uneg);

    int dev = 0, nsm = 148;
    cudaGetDevice(&dev);
    cudaDeviceGetAttribute(&nsm, cudaDevAttrMultiProcessorCount, dev);

    k_main<<<nsm, 256>>>(u, td, tbar, tcur, uneg, z0,
                         Wh, bh, We2n, be2n, Wre, bre, Wrn, brn,
                         Wt, bt, Wom, bom, wt, alpha, psi, out);

    k_scatter<<<HSIZE, 64>>>(out + BDIM + BDIM * NEGK);
}

// round 4
// speedup vs baseline: 1.6771x; 1.6771x over previous
#include <cuda_runtime.h>
#include <math.h>

// Problem constants (fixed shapes per reference)
#define BDIM    512          // number of events (scan length)
#define DEG     16           // neighbors per event
#define NSLOT   17           // write slots per step: w=0 event, w=1..16 neighbors
#define NREAD   22           // read slots per step: 17 (u) + 5 (u_neg)
#define NEGK    5
#define H       256
#define NNODES  200000
#define HBITS   15
#define HSIZE   (1 << HBITS)
#define HMASK   (HSIZE - 1)
#define HK      16           // max writers tracked per row
#define CPR     256          // z0-copy rows per work chunk
#define NCHUNK  ((NNODES + CPR - 1) / CPR)     // 782
#define TOTAL_WORK (BDIM + NCHUNK)             // 1294 (interleaved ids)
#define NTHR    512

// ------------------------- persistent device state -------------------------
__device__ __align__(16) float g_staging[BDIM][NSLOT][H];   // 8.9 MB
__device__ int g_done[BDIM];
__device__ int g_src[BDIM][NREAD];     // -1 => z0[row], else (t'<<5)|w'
__device__ int g_ctr;
__device__ int g_hrow[HSIZE];
__device__ int g_hcnt[HSIZE];
__device__ int g_hent[HSIZE][HK];      // e = (t<<10)|(prio<<5)|w

// ------------------------------- helpers -----------------------------------
__device__ __forceinline__ unsigned hashrow(int row) {
    return ((unsigned)row * 2654435761u) >> (32 - HBITS);
}
__device__ __forceinline__ int ld_acq(const int* p) {
    int v; asm volatile("ld.acquire.gpu.b32 %0, [%1];" : "=r"(v) : "l"(p) : "memory"); return v;
}
__device__ __forceinline__ void st_rel(int* p, int v) {
    asm volatile("st.release.gpu.b32 [%0], %1;" :: "l"(p), "r"(v) : "memory");
}
__device__ __forceinline__ void upk2(unsigned long long v, float& lo, float& hi) {
    asm("mov.b64 {%0, %1}, %2;" : "=f"(lo), "=f"(hi) : "l"(v));
}
// packed fp32x2 FMA: d = a*b + d  (2x FFMA throughput on sm_103a)
__device__ __forceinline__ void fma2(unsigned long long& d, unsigned long long a, unsigned long long b) {
    asm("fma.rn.f32x2 %0, %1, %2, %0;" : "+l"(d) : "l"(a), "l"(b));
}
__device__ __forceinline__ float sigmoidf_(float x) { return 1.0f / (1.0f + expf(-x)); }

// ------------------------------- kernels -----------------------------------
__global__ void k_clear() {
    int i = blockIdx.x * blockDim.x + threadIdx.x;
    if (i < HSIZE) { g_hrow[i] = -1; g_hcnt[i] = 0; }
    if (i < BDIM) g_done[i] = 0;
    if (i == 0) g_ctr = 0;
}

__global__ void k_insert(const int* __restrict__ u) {
    int idx = blockIdx.x * blockDim.x + threadIdx.x;
    if (idx >= BDIM * NSLOT) return;
    int t = idx / NSLOT, w = idx % NSLOT;
    int row = u[t * NSLOT + w];
    int prio = (w == 0) ? 16 : (w - 1);            // event applied last; later neighbor wins
    int e = (t << 10) | (prio << 5) | w;
    unsigned hsh = hashrow(row);
    for (;;) {
        int cur = atomicCAS(&g_hrow[hsh], -1, row);
        if (cur == -1 || cur == row) {
            int c = atomicAdd(&g_hcnt[hsh], 1);
            if (c < HK) g_hent[hsh][c] = e;
            break;
        }
        hsh = (hsh + 1) & HMASK;
    }
}

__global__ void k_resolve(const int* __restrict__ u, const int* __restrict__ u_neg) {
    int idx = blockIdx.x * blockDim.x + threadIdx.x;
    if (idx >= BDIM * NREAD) return;
    int t = idx / NREAD, r = idx % NREAD;
    int row = (r < NSLOT) ? u[t * NSLOT + r] : u_neg[t * NEGK + (r - NSLOT)];
    unsigned hsh = hashrow(row);
    int src = -1, bestkey = -1;
    for (;;) {
        int cur = g_hrow[hsh];
        if (cur == -1) break;
        if (cur == row) {
            int c = g_hcnt[hsh]; if (c > HK) c = HK;
            for (int i = 0; i < c; ++i) {
                int e = g_hent[hsh][i];
                if ((e >> 10) < t) {
                    int key = e >> 5;
                    if (key > bestkey) { bestkey = key; src = ((e >> 10) << 5) | (e & 31); }
                }
            }
            break;
        }
        hsh = (hsh + 1) & HMASK;
    }
    g_src[t][r] = src;
}

// Persistent main kernel, 512 threads/CTA.
// Thread layout for steps: h = tid&255 (output column), jh = tid>>8 (j-half of GEMM).
// Work ids interleave steps and copy chunks 2:3 so DRAM copy overlaps L2-bound steps.
__global__ void __launch_bounds__(NTHR, 1) k_main(
    const int* __restrict__ u, const float* __restrict__ td,
    const float* __restrict__ time_bar, const float* __restrict__ time_cur,
    const int* __restrict__ u_neg, const float* __restrict__ z0,
    const float* __restrict__ Wh,   const float* __restrict__ bh,
    const float* __restrict__ We2n, const float* __restrict__ be2n,
    const float* __restrict__ Wre,  const float* __restrict__ bre,
    const float* __restrict__ Wrn,  const float* __restrict__ brn,
    const float* __restrict__ Wt,   const float* __restrict__ bt,
    const float* __restrict__ Wom,  const float* __restrict__ bom_p,
    const float* __restrict__ wt_p, const float* __restrict__ alpha_p,
    const float* __restrict__ psi_p, float* __restrict__ out)
{
    __shared__ __align__(16) float s_znb[DEG][H];
    __shared__ __align__(16) float s_emb[H];
    __shared__ __align__(16) float s_mean[H];
    __shared__ __align__(16) float s_cmn[H];
    __shared__ float s_td[NSLOT][4];
    __shared__ int s_step;

    const int tid  = threadIdx.x;
    const int lane = tid & 31, wid = tid >> 5;
    const int h    = tid & 255, jh = tid >> 8;
    const float w_t = *wt_p, alpha = *alpha_p, psi = *psi_p;
    const float bom = *bom_p;
    const float inv_psi = 1.0f / (psi + 1e-7f);
    float* outz = out + (BDIM + BDIM * NEGK);

    for (;;) {
        __syncthreads();                      // protect s_step / smem reuse
        if (tid == 0) s_step = atomicAdd(&g_ctr, 1);
        __syncthreads();
        const int id = s_step;
        if (id >= TOTAL_WORK) break;

        // decode interleaved work id -> step s or copy chunk
        int s = -1, chunk = -1;
        if (id < 1280) {
            int q = id / 5, r = id % 5;
            if (r < 2) s = q * 2 + r;
            else       chunk = q * 3 + (r - 2);
        } else {
            chunk = 768 + (id - 1280);
        }

        if (chunk >= 0) {
            // ---- streaming copy chunk: z0 rows -> z_final region of out ----
            size_t r0 = (size_t)chunk * CPR;
            int nrow = (NNODES - (int)r0 > CPR) ? CPR : (NNODES - (int)r0);
            const float4* src = (const float4*)z0 + r0 * (H / 4);
            float4*       dst = (float4*)outz  + r0 * (H / 4);
            int n4 = nrow * (H / 4);                      // 16384 or 4096
            for (int base = 0; base < n4; base += NTHR * 8) {
                float4 t[8];
                #pragma unroll
                for (int b = 0; b < 8; ++b) {
                    int i = base + tid + b * NTHR;
                    if (i < n4) t[b] = __ldcs(&src[i]);
                }
                #pragma unroll
                for (int b = 0; b < 8; ++b) {
                    int i = base + tid + b * NTHR;
                    if (i < n4) __stcs(&dst[i], t[b]);
                }
            }
            continue;
        }

        // ---------------- event step s ----------------
        if (tid < NREAD) {                       // wait for producer steps (rare)
            int sv = g_src[s][tid];
            if (sv >= 0) {
                int* flag = &g_done[sv >> 5];
                while (ld_acq(flag) == 0) __nanosleep(64);
            }
        }
        if (tid >= 32 && tid < 32 + NSLOT * 4) { // normalized time deltas
            int q = tid - 32;
            const float inv_sd[4] = {1.f/50.f, 1.f/7.f, 1.f/15.f, 1.f/15.f};
            s_td[q >> 2][q & 3] = td[(s * NSLOT + (q >> 2)) * 4 + (q & 3)] * inv_sd[q & 3];
        }
        __syncthreads();

        // load the 17 rows (emb_u + 16 neighbors); one warp per row
        for (int r = wid; r < NSLOT; r += 16) {
            int sv = g_src[s][r];
            const float4* src4 = (sv >= 0)
                ? (const float4*)g_staging[sv >> 5][sv & 31]
                : (const float4*)(z0 + (size_t)u[s * NSLOT + r] * H);
            float4* dst4 = (r == 0) ? (float4*)s_emb : (float4*)s_znb[r - 1];
            dst4[lane]      = src4[lane];
            dst4[lane + 32] = src4[lane + 32];
        }
        __syncthreads();

        // mean over neighbor rows (tid<256) || Hawkes lambdas (warps 8..13)
        if (tid < H) {
            float acc = 0.f;
            #pragma unroll
            for (int j = 0; j < DEG; ++j) acc += s_znb[j][tid];
            s_mean[tid] = acc * (1.0f / DEG);
        } else if (wid >= 8 && wid < 8 + NEGK) {
            int nw = wid - 8;
            int node = u_neg[s * NEGK + nw];
            int sv = g_src[s][NSLOT + nw];
            const float* srcp = (sv >= 0) ? g_staging[sv >> 5][sv & 31]
                                          : (z0 + (size_t)node * H);
            float acc = 0.f;
            for (int i = lane; i < H; i += 32) acc += srcp[i] * Wom[i];
            #pragma unroll
            for (int o = 16; o; o >>= 1) acc += __shfl_down_sync(0xffffffffu, acc, o);
            if (lane == 0) {
                float ts = time_cur[s] - time_bar[(size_t)s * NNODES + node];
                float g = acc + bom + alpha * expf(-w_t * (ts * (1.0f / 86400.0f)));
                float gp = fminf(fmaxf(g * inv_psi, -75.f), 75.f);
                out[BDIM + s * NEGK + nw] = psi * log1pf(expf(gp)) * (1.0f / NEGK);
            }
        } else if (wid == 13) {
            float acc = 0.f;
            for (int i = lane; i < H; i += 32) acc += s_emb[i] * Wom[i];
            #pragma unroll
            for (int o = 16; o; o >>= 1) acc += __shfl_down_sync(0xffffffffu, acc, o);
            if (lane == 0) {
                float ts = time_cur[s] - s_td[0][0];
                float g = acc + bom + alpha * expf(-w_t * (ts * (1.0f / 86400.0f)));
                float gp = fminf(fmaxf(g * inv_psi, -75.f), 75.f);
                out[s] = psi * log1pf(expf(gp));
            }
        }
        __syncthreads();     // s_mean ready

        // time-feature weights for this column (both halves need them)
        float4 wtr = *(const float4*)(Wt + (size_t)h * 4);
        float btv = bt[h];

        // ---- split matvecs: jh=0 -> Wh*mean + Wre*emb (z_ev); jh=1 -> We2n*emb (s_cmn)
        if (jh == 0) {
            unsigned long long acc_h = 0ull, acc_e = 0ull;
            const ulonglong2* wh2 = (const ulonglong2*)(Wh  + (size_t)h * H);
            const ulonglong2* we2 = (const ulonglong2*)(Wre + (size_t)h * H);
            const ulonglong2* m2  = (const ulonglong2*)s_mean;
            const ulonglong2* e2  = (const ulonglong2*)s_emb;
            #pragma unroll 4
            for (int i4 = 0; i4 < H / 4; ++i4) {
                ulonglong2 a = wh2[i4], b = we2[i4];
                ulonglong2 m = m2[i4],  e = e2[i4];
                fma2(acc_h, a.x, m.x); fma2(acc_h, a.y, m.y);
                fma2(acc_e, b.x, e.x); fma2(acc_e, b.y, e.y);
            }
            float hl, hh, el, eh;
            upk2(acc_h, hl, hh); upk2(acc_e, el, eh);
            float tf0 = btv + wtr.x*s_td[0][0] + wtr.y*s_td[0][1]
                            + wtr.z*s_td[0][2] + wtr.w*s_td[0][3];
            g_staging[s][0][h] = sigmoidf_((hl + hh) + bh[h] + (el + eh) + bre[h] + tf0);
        } else {
            unsigned long long acc_n = 0ull;
            const ulonglong2* wn2 = (const ulonglong2*)(We2n + (size_t)h * H);
            const ulonglong2* e2  = (const ulonglong2*)s_emb;
            #pragma unroll 4
            for (int i4 = 0; i4 < H / 4; ++i4) {
                ulonglong2 c = wn2[i4];
                ulonglong2 e = e2[i4];
                fma2(acc_n, c.x, e.x); fma2(acc_n, c.y, e.y);
            }
            float nl, nh; upk2(acc_n, nl, nh);
            s_cmn[h] = (nl + nh) + be2n[h] + brn[h];
        }
        __syncthreads();     // s_cmn ready

        // ---- main GEMM: this thread computes 8 j-rows for column h ----
        const int jbase = jh * 8;
        unsigned long long acc2[8];
        #pragma unroll
        for (int jj = 0; jj < 8; ++jj) acc2[jj] = 0ull;
        const ulonglong2* wr2 = (const ulonglong2*)(Wrn + (size_t)h * H);
        #pragma unroll 4
        for (int i4 = 0; i4 < H / 4; ++i4) {
            ulonglong2 w = wr2[i4];
            #pragma unroll
            for (int jj = 0; jj < 8; ++jj) {
                ulonglong2 z = *(const ulonglong2*)&s_znb[jbase + jj][i4 * 4]; // LDS.128 broadcast
                fma2(acc2[jj], w.x, z.x);
                fma2(acc2[jj], w.y, z.y);
            }
        }
        float cmn = s_cmn[h];
        #pragma unroll
        for (int jj = 0; jj < 8; ++jj) {
            int j = jbase + jj;
            float lo, hi; upk2(acc2[jj], lo, hi);
            float tf = btv + wtr.x*s_td[1+j][0] + wtr.y*s_td[1+j][1]
                           + wtr.z*s_td[1+j][2] + wtr.w*s_td[1+j][3];
            g_staging[s][1 + j][h] = sigmoidf_(lo + hi + cmn + tf);
        }

        __threadfence();
        __syncthreads();
        if (tid == 0) st_rel(&g_done[s], 1);
    }
}

// Scatter final row versions (last writer per touched row) over the copied z0.
__global__ void k_scatter(float* __restrict__ outz) {
    int b = blockIdx.x;
    int c = g_hcnt[b];
    if (c <= 0) return;
    if (c > HK) c = HK;
    int bestkey = -1, beste = 0;
    for (int i = 0; i < c; ++i) {
        int e = g_hent[b][i];
        int key = e >> 5;
        if (key > bestkey) { bestkey = key; beste = e; }
    }
    int t = beste >> 10, w = beste & 31;
    int row = g_hrow[b];
    const float4* src = (const float4*)g_staging[t][w];
    float4* dst = (float4*)outz + (size_t)row * (H / 4);
    dst[threadIdx.x] = src[threadIdx.x];
}

// ------------------------------- launch ------------------------------------
extern "C" void kernel_launch(void* const* d_in, const int* in_sizes, int n_in,
                              void* d_out, int out_size) {
    const int*   u     = (const int*)  d_in[0];
    const float* td    = (const float*)d_in[1];
    const float* tbar  = (const float*)d_in[2];
    const float* tcur  = (const float*)d_in[3];
    // d_in[4] significance, d_in[5] magnitudo: unused by reference
    const int*   uneg  = (const int*)  d_in[6];
    const float* z0    = (const float*)d_in[7];
    const float* Wh    = (const float*)d_in[8];
    const float* bh    = (const float*)d_in[9];
    const float* We2n  = (const float*)d_in[10];
    const float* be2n  = (const float*)d_in[11];
    const float* Wre   = (const float*)d_in[12];
    const float* bre   = (const float*)d_in[13];
    const float* Wrn   = (const float*)d_in[14];
    const float* brn   = (const float*)d_in[15];
    const float* Wt    = (const float*)d_in[16];
    const float* bt    = (const float*)d_in[17];
    const float* Wom   = (const float*)d_in[18];
    const float* bom   = (const float*)d_in[19];
    const float* wt    = (const float*)d_in[20];
    const float* alpha = (const float*)d_in[21];
    const float* psi   = (const float*)d_in[22];
    float* out = (float*)d_out;

    k_clear  <<<(HSIZE + 255) / 256, 256>>>();
    k_insert <<<(BDIM * NSLOT + 255) / 256, 256>>>(u);
    k_resolve<<<(BDIM * NREAD + 255) / 256, 256>>>(u, uneg);

    int dev = 0, nsm = 148;
    cudaGetDevice(&dev);
    cudaDeviceGetAttribute(&nsm, cudaDevAttrMultiProcessorCount, dev);

    k_main<<<nsm, NTHR>>>(u, td, tbar, tcur, uneg, z0,
                          Wh, bh, We2n, be2n, Wre, bre, Wrn, brn,
                          Wt, bt, Wom, bom, wt, alpha, psi, out);

    k_scatter<<<HSIZE, 64>>>(out + BDIM + BDIM * NEGK);
}